// round 6
// baseline (speedup 1.0000x reference)
#include <cuda_runtime.h>
#include <cuda_bf16.h>
#include <mma.h>
#include <cstdint>

using namespace nvcuda;

typedef unsigned long long u64;

// ---------------- packed f32x2 helpers ----------------
__device__ __forceinline__ u64 pk2(float a, float b) {
    u64 r; asm("mov.b64 %0, {%1,%2};" : "=l"(r) : "f"(a), "f"(b)); return r;
}
__device__ __forceinline__ void upk2(u64 v, float& a, float& b) {
    asm("mov.b64 {%0,%1}, %2;" : "=f"(a), "=f"(b) : "l"(v));
}
__device__ __forceinline__ u64 ffma2(u64 a, u64 b, u64 c) {
    u64 d; asm("fma.rn.f32x2 %0, %1, %2, %3;" : "=l"(d) : "l"(a), "l"(b), "l"(c)); return d;
}
__device__ __forceinline__ u64 fmul2(u64 a, u64 b) {
    u64 d; asm("mul.rn.f32x2 %0, %1, %2;" : "=l"(d) : "l"(a), "l"(b)); return d;
}
__device__ __forceinline__ u64 fadd2(u64 a, u64 b) {
    u64 d; asm("add.rn.f32x2 %0, %1, %2;" : "=l"(d) : "l"(a), "l"(b)); return d;
}
__device__ __forceinline__ float tanh_(float x) {
    float t; asm("tanh.approx.f32 %0, %1;" : "=f"(t) : "f"(x)); return t;
}

#define H    1024
#define DIN  784
#define DOUT 10
#define MAXB 16384
#define KPAD 832          // 784 padded; rows stay 16B-aligned

__device__ float g_xW1[(size_t)MAXB * H];                        // x @ W1 (fp32)
__device__ __align__(16) __nv_bfloat16 g_xh[(size_t)MAXB * KPAD];
__device__ __align__(16) __nv_bfloat16 g_xl[(size_t)MAXB * KPAD];
__device__ __align__(16) __nv_bfloat16 g_wh[(size_t)H * KPAD];   // W1^T hi  [n][k]
__device__ __align__(16) __nv_bfloat16 g_wl[(size_t)H * KPAD];   // W1^T lo  [n][k]

// ==================== conversion kernels ====================
__global__ __launch_bounds__(256) void conv_x(const float* __restrict__ x, int B) {
    int u = blockIdx.x * 256 + threadIdx.x;
    if (u >= B * 208) return;                 // 208 = KPAD/4 float4-units per row
    int m = u / 208, ku = u - m * 208;
    ushort4 hh = {0, 0, 0, 0}, ll = {0, 0, 0, 0};
    if (ku < 196) {                           // 784/4 real units
        float4 v = *(const float4*)(x + (size_t)m * DIN + ku * 4);
        __nv_bfloat16 h0 = __float2bfloat16(v.x), h1 = __float2bfloat16(v.y);
        __nv_bfloat16 h2 = __float2bfloat16(v.z), h3 = __float2bfloat16(v.w);
        __nv_bfloat16 l0 = __float2bfloat16(v.x - __bfloat162float(h0));
        __nv_bfloat16 l1 = __float2bfloat16(v.y - __bfloat162float(h1));
        __nv_bfloat16 l2 = __float2bfloat16(v.z - __bfloat162float(h2));
        __nv_bfloat16 l3 = __float2bfloat16(v.w - __bfloat162float(h3));
        hh = make_ushort4(__bfloat16_as_ushort(h0), __bfloat16_as_ushort(h1),
                          __bfloat16_as_ushort(h2), __bfloat16_as_ushort(h3));
        ll = make_ushort4(__bfloat16_as_ushort(l0), __bfloat16_as_ushort(l1),
                          __bfloat16_as_ushort(l2), __bfloat16_as_ushort(l3));
    }
    *(ushort4*)(g_xh + (size_t)m * KPAD + ku * 4) = hh;
    *(ushort4*)(g_xl + (size_t)m * KPAD + ku * 4) = ll;
}

__global__ __launch_bounds__(256) void conv_w1t(const float* __restrict__ W1) {
    int u = blockIdx.x * 256 + threadIdx.x;
    if (u >= H * KPAD) return;
    int n = u / KPAD, k = u - n * KPAD;
    __nv_bfloat16 h = __ushort_as_bfloat16(0), l = __ushort_as_bfloat16(0);
    if (k < DIN) {
        float w = W1[(size_t)k * H + n];
        h = __float2bfloat16(w);
        l = __float2bfloat16(w - __bfloat162float(h));
    }
    g_wh[(size_t)n * KPAD + k] = h;
    g_wl[(size_t)n * KPAD + k] = l;
}

// ==================== split-bf16 mma.sync GEMM: g_xW1 = x @ W1 (unchanged R5) ====================
#define TSTRIDE 24   // smem row stride in bf16: 48B = 16B-aligned, conflict-distinct rows

__global__ __launch_bounds__(256, 2) void mma_xw1() {
    __shared__ __nv_bfloat16 sAh[128 * TSTRIDE];
    __shared__ __nv_bfloat16 sAl[128 * TSTRIDE];
    __shared__ __nv_bfloat16 sBh[128 * TSTRIDE];
    __shared__ __nv_bfloat16 sBl[128 * TSTRIDE];

    const int tid  = threadIdx.x;
    const int warp = tid >> 5;
    const int m0 = blockIdx.y * 128;
    const int n0 = blockIdx.x * 128;
    const int wm = (warp >> 2) * 64;
    const int wn = (warp & 3) * 32;

    wmma::fragment<wmma::accumulator, 16, 16, 16, float> acc[4][2];
#pragma unroll
    for (int i = 0; i < 4; ++i)
#pragma unroll
        for (int j = 0; j < 2; ++j) wmma::fill_fragment(acc[i][j], 0.0f);

    const int row = tid >> 1;
    const int ch  = (tid & 1) * 8;
    const __nv_bfloat16* gah = g_xh + (size_t)(m0 + row) * KPAD + ch;
    const __nv_bfloat16* gal = g_xl + (size_t)(m0 + row) * KPAD + ch;
    const __nv_bfloat16* gbh = g_wh + (size_t)(n0 + row) * KPAD + ch;
    const __nv_bfloat16* gbl = g_wl + (size_t)(n0 + row) * KPAD + ch;
    const int sdst = row * TSTRIDE + ch;

    uint4 pah = *(const uint4*)gah;
    uint4 pal = *(const uint4*)gal;
    uint4 pbh = *(const uint4*)gbh;
    uint4 pbl = *(const uint4*)gbl;

    for (int k0 = 0; k0 < DIN; k0 += 16) {
        *(uint4*)&sAh[sdst] = pah;
        *(uint4*)&sAl[sdst] = pal;
        *(uint4*)&sBh[sdst] = pbh;
        *(uint4*)&sBl[sdst] = pbl;
        __syncthreads();

        int kn = k0 + 16;
        if (kn < DIN) {
            pah = *(const uint4*)(gah + kn);
            pal = *(const uint4*)(gal + kn);
            pbh = *(const uint4*)(gbh + kn);
            pbl = *(const uint4*)(gbl + kn);
        }

        wmma::fragment<wmma::matrix_b, 16, 16, 16, __nv_bfloat16, wmma::col_major> bh[2], bl[2];
#pragma unroll
        for (int j = 0; j < 2; ++j) {
            wmma::load_matrix_sync(bh[j], &sBh[(wn + j * 16) * TSTRIDE], TSTRIDE);
            wmma::load_matrix_sync(bl[j], &sBl[(wn + j * 16) * TSTRIDE], TSTRIDE);
        }
#pragma unroll
        for (int i = 0; i < 4; ++i) {
            wmma::fragment<wmma::matrix_a, 16, 16, 16, __nv_bfloat16, wmma::row_major> ah, al;
            wmma::load_matrix_sync(ah, &sAh[(wm + i * 16) * TSTRIDE], TSTRIDE);
            wmma::load_matrix_sync(al, &sAl[(wm + i * 16) * TSTRIDE], TSTRIDE);
#pragma unroll
            for (int j = 0; j < 2; ++j) {
                wmma::mma_sync(acc[i][j], ah, bh[j], acc[i][j]);
                wmma::mma_sync(acc[i][j], ah, bl[j], acc[i][j]);
                wmma::mma_sync(acc[i][j], al, bh[j], acc[i][j]);
            }
        }
        __syncthreads();
    }

#pragma unroll
    for (int i = 0; i < 4; ++i)
#pragma unroll
        for (int j = 0; j < 2; ++j) {
            float* C = g_xW1 + (size_t)(m0 + wm + i * 16) * H + (n0 + wn + j * 16);
            wmma::store_matrix_sync(C, acc[i][j], H, wmma::mem_row_major);
        }
}

// ==================== Kernel 2: 50-step settle, 512 threads / 2 cols per thread ====================
// Same 4 rows/CTA and phase structure as R3, but thread state halves (w2p 20 regs,
// u1v 8) so __launch_bounds__(512,2) holds 64 regs -> 32 warps/SM (2x occupancy).
// 2-level butterfly (shfl 16, 8); lanes 0-7 of 16 warps give the same 128 partials
// per (r,k) and identical wpart layout, so phase B is byte-identical to R3.
__global__ __launch_bounds__(512, 2) void settle_kernel(
    const float* __restrict__ u1g, const float* __restrict__ u2g,
    const float* __restrict__ W2g, const float* __restrict__ b1g,
    const float* __restrict__ b2g, const int* __restrict__ steps_p,
    float* __restrict__ outg)
{
    __shared__ float c1_s[4 * H];
    __shared__ __align__(16) float r2_s[4][12];
    __shared__ u64 wpart[80 * 33];

    const int tid  = threadIdx.x;
    const int lane = tid & 31;
    const int wid  = tid >> 5;
    const int b0   = blockIdx.x * 4;
    const int nsteps = *steps_p;

    // ---- W2/16 rows (packed) for this thread's 2 columns ----
    u64 w2p[2][5];
#pragma unroll
    for (int j = 0; j < 2; ++j) {
        const float* w = W2g + (tid + 512 * j) * DOUT;
#pragma unroll
        for (int k = 0; k < 5; ++k)
            w2p[j][k] = pk2(w[2 * k] * 0.0625f, w[2 * k + 1] * 0.0625f);
    }

    // ---- state v = u1/2 ----
    float u1v[4][2];
#pragma unroll
    for (int r = 0; r < 4; ++r)
#pragma unroll
        for (int j = 0; j < 2; ++j)
            u1v[r][j] = 0.5f * u1g[(size_t)(b0 + r) * H + tid + 512 * j];

    // ---- c1 = (0.5*xW1 + b1)/16 -> SMEM ----
    {
        const float4* xs = (const float4*)(g_xW1 + (size_t)b0 * H);
        const float4* bs = (const float4*)b1g;
        float4* dst = (float4*)c1_s;
#pragma unroll
        for (int i = 0; i < 2; ++i) {
            int e = tid + 512 * i;
            float4 xv = xs[e];
            float4 bv = bs[e & 255];
            dst[e] = make_float4(fmaf(0.03125f, xv.x, 0.0625f * bv.x),
                                 fmaf(0.03125f, xv.y, 0.0625f * bv.y),
                                 fmaf(0.03125f, xv.z, 0.0625f * bv.z),
                                 fmaf(0.03125f, xv.w, 0.0625f * bv.w));
        }
    }

    // ---- phase-B mapping (identical to R3): 160 threads, 4 per (r,o) ----
    const bool pb = tid < 160;
    const int r_b  = tid / 40;
    const int rem  = tid - 40 * r_b;
    const int o_b  = rem >> 2;
    const int q4   = rem & 3;
    const int k_b  = o_b >> 1;
    const int half = o_b & 1;
    const float* fb = (const float*)(wpart + ((size_t)((r_b * 5 + k_b) * 4 + q4)) * 33);
    const float* fb_pre = (const float*)(wpart + ((size_t)(k_b * 4 + q4)) * 33);

    // ---- pre-pass: colsum(W2)/16 (r=0 slots) ----
    {
        u64 qa[5];
#pragma unroll
        for (int k = 0; k < 5; ++k)
            qa[k] = fadd2(w2p[0][k], w2p[1][k]);
#pragma unroll
        for (int off = 16; off >= 8; off >>= 1)
#pragma unroll
            for (int k = 0; k < 5; ++k)
                qa[k] = fadd2(qa[k], __shfl_xor_sync(0xffffffffu, qa[k], off));
        if (lane < 8) {
            int pIdx = wid * 8 + lane;
            int chunk = pIdx >> 5, pos = pIdx & 31;
#pragma unroll
            for (int k = 0; k < 5; ++k)
                wpart[(k * 4 + chunk) * 33 + pos] = qa[k];
        }
    }
    __syncthreads();

    float C2v = 0.0f, wv = 0.0f, r2v = 0.0f;
    if (pb) {
        float s0a = 0, s0b = 0, s1a = 0, s1b = 0;
#pragma unroll
        for (int i = 0; i < 16; ++i) {
            float2 za = *(const float2*)(fb_pre + 4 * i);
            float2 zb = *(const float2*)(fb_pre + 4 * i + 2);
            s0a += za.x; s1a += za.y; s0b += zb.x; s1b += zb.y;
        }
        float s = half ? (s1a + s1b) : (s0a + s0b);
        s += __shfl_xor_sync(0xffffffffu, s, 1);
        s += __shfl_xor_sync(0xffffffffu, s, 2);
        C2v = fmaf(8.0f, s, b2g[o_b]);
        wv  = 0.5f * u2g[(b0 + r_b) * DOUT + o_b];
        float tau = tanh_(wv);
        r2v = fmaf(0.5f, tau, 0.5f);
        if (q4 == 0) r2_s[r_b][o_b] = r2v;
    }
    __syncthreads();

    for (int s = 0; s < nsteps; ++s) {
        // ---------- phase A ----------
#pragma unroll
        for (int r = 0; r < 4; ++r) {
            ulonglong2 ra = *(const ulonglong2*)&r2_s[r][0];
            ulonglong2 rb = *(const ulonglong2*)&r2_s[r][4];
            u64 rc = *(const u64*)&r2_s[r][8];
            u64 r2p[5] = {ra.x, ra.y, rb.x, rb.y, rc};
            u64 qacc[5] = {0ULL, 0ULL, 0ULL, 0ULL, 0ULL};
#pragma unroll
            for (int j = 0; j < 2; ++j) {
                float v  = u1v[r][j];
                float th = tanh_(v);
                u64 p2 = fmul2(w2p[j][0], r2p[0]);
                p2 = ffma2(w2p[j][1], r2p[1], p2);
                p2 = ffma2(w2p[j][2], r2p[2], p2);
                p2 = ffma2(w2p[j][3], r2p[3], p2);
                p2 = ffma2(w2p[j][4], r2p[4], p2);
                float pa, pb2; upk2(p2, pa, pb2);
                u64 th2 = pk2(th, th);
#pragma unroll
                for (int k = 0; k < 5; ++k) qacc[k] = ffma2(th2, w2p[j][k], qacc[k]);
                float t   = (pa + pb2) + c1_s[r * H + tid + 512 * j];
                float omt = fmaf(-th, th, 1.0f);
                u1v[r][j] = fmaf(omt, t, 0.5f * v);
            }
            // 2-level butterfly -> lanes 0-7 hold partials; 16 warps x 8 = 128
#pragma unroll
            for (int off = 16; off >= 8; off >>= 1)
#pragma unroll
                for (int k = 0; k < 5; ++k)
                    qacc[k] = fadd2(qacc[k], __shfl_xor_sync(0xffffffffu, qacc[k], off));
            if (lane < 8) {
                int pIdx = wid * 8 + lane;
                int chunk = pIdx >> 5, pos = pIdx & 31;
#pragma unroll
                for (int k = 0; k < 5; ++k)
                    wpart[((r * 5 + k) * 4 + chunk) * 33 + pos] = qacc[k];
            }
        }
        __syncthreads();

        // ---------- phase B (identical to R3) ----------
        if (pb) {
            float s0a = 0, s0b = 0, s1a = 0, s1b = 0;
#pragma unroll
            for (int i = 0; i < 16; ++i) {
                float2 za = *(const float2*)(fb + 4 * i);
                float2 zb = *(const float2*)(fb + 4 * i + 2);
                s0a += za.x; s1a += za.y; s0b += zb.x; s1b += zb.y;
            }
            float sv = half ? (s1a + s1b) : (s0a + s0b);
            sv += __shfl_xor_sync(0xffffffffu, sv, 1);
            sv += __shfl_xor_sync(0xffffffffu, sv, 2);
            float gq  = fmaf(8.0f, sv, C2v);
            float tau = tanh_(wv);
            float om  = fmaf(-tau, tau, 1.0f);
            wv = fmaf(0.0625f * om, gq, 0.5f * wv);
            r2v = fmaf(0.5f, tanh_(wv), 0.5f);
            if (q4 == 0) r2_s[r_b][o_b] = r2v;
        }
        __syncthreads();
    }

    if (pb && q4 == 0)
        outg[(b0 + r_b) * DOUT + o_b] = r2v;
}

// ==================== launch ====================
extern "C" void kernel_launch(void* const* d_in, const int* in_sizes, int n_in,
                              void* d_out, int out_size) {
    const float* x     = (const float*)d_in[0];
    const float* u1    = (const float*)d_in[1];
    const float* u2    = (const float*)d_in[2];
    const float* W1    = (const float*)d_in[3];
    const float* W2    = (const float*)d_in[4];
    const float* b1    = (const float*)d_in[5];
    const float* b2    = (const float*)d_in[6];
    const int*   steps = (const int*)d_in[7];
    float* out = (float*)d_out;

    const int B = in_sizes[1] / H;

    conv_x<<<(B * 208 + 255) / 256, 256>>>(x, B);
    conv_w1t<<<(H * KPAD + 255) / 256, 256>>>(W1);
    mma_xw1<<<dim3(H / 128, B / 128), 256>>>();
    settle_kernel<<<B / 4, 512>>>(u1, u2, W2, b1, b2, steps, out);
}

// round 7
// speedup vs baseline: 1.5331x; 1.5331x over previous
#include <cuda_runtime.h>
#include <cuda_bf16.h>
#include <mma.h>
#include <cstdint>

using namespace nvcuda;

typedef unsigned long long u64;

// ---------------- packed f32x2 helpers ----------------
__device__ __forceinline__ u64 pk2(float a, float b) {
    u64 r; asm("mov.b64 %0, {%1,%2};" : "=l"(r) : "f"(a), "f"(b)); return r;
}
__device__ __forceinline__ void upk2(u64 v, float& a, float& b) {
    asm("mov.b64 {%0,%1}, %2;" : "=f"(a), "=f"(b) : "l"(v));
}
__device__ __forceinline__ u64 ffma2(u64 a, u64 b, u64 c) {
    u64 d; asm("fma.rn.f32x2 %0, %1, %2, %3;" : "=l"(d) : "l"(a), "l"(b), "l"(c)); return d;
}
__device__ __forceinline__ u64 fmul2(u64 a, u64 b) {
    u64 d; asm("mul.rn.f32x2 %0, %1, %2;" : "=l"(d) : "l"(a), "l"(b)); return d;
}
__device__ __forceinline__ u64 fadd2(u64 a, u64 b) {
    u64 d; asm("add.rn.f32x2 %0, %1, %2;" : "=l"(d) : "l"(a), "l"(b)); return d;
}
__device__ __forceinline__ float tanh_(float x) {
    float t; asm("tanh.approx.f32 %0, %1;" : "=f"(t) : "f"(x)); return t;
}

#define H    1024
#define DIN  784
#define DOUT 10
#define MAXB 16384
#define KPAD 832          // W1^T row stride (16B-aligned)
#define NK   49           // 49 * 16 = 784 exactly

__device__ float g_xW1[(size_t)MAXB * H];                        // x @ W1 (fp32)
__device__ __align__(16) __nv_bfloat16 g_wh[(size_t)H * KPAD];   // W1^T hi  [n][k]
__device__ __align__(16) __nv_bfloat16 g_wl[(size_t)H * KPAD];   // W1^T lo  [n][k]

// ==================== conv: W1 -> W1^T hi/lo bf16 (one-time, 6.5 MB) ====================
__global__ __launch_bounds__(256) void conv_w1t(const float* __restrict__ W1) {
    int u = blockIdx.x * 256 + threadIdx.x;
    if (u >= H * KPAD) return;
    int n = u / KPAD, k = u - n * KPAD;
    __nv_bfloat16 h = __ushort_as_bfloat16(0), l = __ushort_as_bfloat16(0);
    if (k < DIN) {
        float w = W1[(size_t)k * H + n];
        h = __float2bfloat16(w);
        l = __float2bfloat16(w - __bfloat162float(h));
    }
    g_wh[(size_t)n * KPAD + k] = h;
    g_wl[(size_t)n * KPAD + k] = l;
}

// ==================== split-bf16 mma.sync GEMM, cp.async pipelined ====================
// g_xW1 = x @ W1. CTA tile 128x128, K-step 16, 49 iters, ONE __syncthreads per iter.
// A (x) loaded fp32 from gmem, hi/lo-split in registers, STS one iteration ahead.
// B (W1^T hi/lo) streamed via cp.async.cg into 2-stage buffers.
// acc += Ah*Bh + Ah*Bl + Al*Bh  (fp32 accumulate).
#define TS 16   // smem tile k-stride (bf16 elements)

__device__ __forceinline__ void cp16(uint32_t dst, const void* src) {
    asm volatile("cp.async.cg.shared.global [%0], [%1], 16;" :: "r"(dst), "l"(src));
}

__global__ __launch_bounds__(256, 2) void mma_xw1(const float* __restrict__ x) {
    __shared__ __nv_bfloat16 sAh[2][128 * TS];
    __shared__ __nv_bfloat16 sAl[2][128 * TS];
    __shared__ __nv_bfloat16 sBh[2][128 * TS];
    __shared__ __nv_bfloat16 sBl[2][128 * TS];

    const int tid  = threadIdx.x;
    const int warp = tid >> 5;
    const int m0 = blockIdx.y * 128;
    const int n0 = blockIdx.x * 128;
    const int wm = (warp >> 2) * 64;
    const int wn = (warp & 3) * 32;

    wmma::fragment<wmma::accumulator, 16, 16, 16, float> acc[4][2];
#pragma unroll
    for (int i = 0; i < 4; ++i)
#pragma unroll
        for (int j = 0; j < 2; ++j) wmma::fill_fragment(acc[i][j], 0.0f);

    // fill mapping: 2 threads per row, 8 elements (one 16B bf16 chunk) each
    const int row = tid >> 1;
    const int ch  = (tid & 1) * 8;
    const float* xsrc = x + (size_t)(m0 + row) * DIN + ch;        // + k0 per iter
    const __nv_bfloat16* bhsrc = g_wh + (size_t)(n0 + row) * KPAD + ch;
    const __nv_bfloat16* blsrc = g_wl + (size_t)(n0 + row) * KPAD + ch;
    const int sidx = row * TS + ch;

    // ---- helpers: convert 8 fp32 -> hi/lo bf16 and STS.128 ----
    float4 aPre0, aPre1;          // prefetched A regs (next chunk)
    auto ldA = [&](int it) { aPre0 = *(const float4*)(xsrc + it * 16);
                             aPre1 = *(const float4*)(xsrc + it * 16 + 4); };
    auto stA = [&](int stg) {
        float v[8] = {aPre0.x, aPre0.y, aPre0.z, aPre0.w, aPre1.x, aPre1.y, aPre1.z, aPre1.w};
        ushort4 hA, hB, lA, lB;
        ushort hh[8], ll[8];
#pragma unroll
        for (int i = 0; i < 8; ++i) {
            __nv_bfloat16 h = __float2bfloat16(v[i]);
            __nv_bfloat16 l = __float2bfloat16(v[i] - __bfloat162float(h));
            hh[i] = __bfloat16_as_ushort(h);
            ll[i] = __bfloat16_as_ushort(l);
        }
        hA = make_ushort4(hh[0], hh[1], hh[2], hh[3]);
        hB = make_ushort4(hh[4], hh[5], hh[6], hh[7]);
        lA = make_ushort4(ll[0], ll[1], ll[2], ll[3]);
        lB = make_ushort4(ll[4], ll[5], ll[6], ll[7]);
        *(ushort4*)&sAh[stg][sidx]     = hA;
        *(ushort4*)&sAh[stg][sidx + 4] = hB;
        *(ushort4*)&sAl[stg][sidx]     = lA;
        *(ushort4*)&sAl[stg][sidx + 4] = lB;
    };
    auto cpB = [&](int it, int stg) {
        cp16((uint32_t)__cvta_generic_to_shared(&sBh[stg][sidx]), bhsrc + it * 16);
        cp16((uint32_t)__cvta_generic_to_shared(&sBl[stg][sidx]), blsrc + it * 16);
        asm volatile("cp.async.commit_group;" ::: "memory");
    };

    // ---- prologue: A(0) in smem, B(0) in flight, A(1) in regs ----
    ldA(0); stA(0);
    cpB(0, 0);
    ldA(1);

    for (int it = 0; it < NK; ++it) {
        asm volatile("cp.async.wait_group 0;" ::: "memory");
        __syncthreads();                       // stage[it&1] ready; all reads of stage[(it+1)&1] done
        if (it + 1 < NK) { stA((it + 1) & 1); cpB(it + 1, (it + 1) & 1); }
        if (it + 2 < NK) ldA(it + 2);

        const int st = it & 1;
        wmma::fragment<wmma::matrix_b, 16, 16, 16, __nv_bfloat16, wmma::col_major> bh[2], bl[2];
#pragma unroll
        for (int j = 0; j < 2; ++j) {
            wmma::load_matrix_sync(bh[j], &sBh[st][(wn + j * 16) * TS], TS);
            wmma::load_matrix_sync(bl[j], &sBl[st][(wn + j * 16) * TS], TS);
        }
#pragma unroll
        for (int i = 0; i < 4; ++i) {
            wmma::fragment<wmma::matrix_a, 16, 16, 16, __nv_bfloat16, wmma::row_major> ah, al;
            wmma::load_matrix_sync(ah, &sAh[st][(wm + i * 16) * TS], TS);
            wmma::load_matrix_sync(al, &sAl[st][(wm + i * 16) * TS], TS);
#pragma unroll
            for (int j = 0; j < 2; ++j) {
                wmma::mma_sync(acc[i][j], ah, bh[j], acc[i][j]);
                wmma::mma_sync(acc[i][j], ah, bl[j], acc[i][j]);
                wmma::mma_sync(acc[i][j], al, bh[j], acc[i][j]);
            }
        }
    }

#pragma unroll
    for (int i = 0; i < 4; ++i)
#pragma unroll
        for (int j = 0; j < 2; ++j) {
            float* C = g_xW1 + (size_t)(m0 + wm + i * 16) * H + (n0 + wn + j * 16);
            wmma::store_matrix_sync(C, acc[i][j], H, wmma::mem_row_major);
        }
}

// ==================== Kernel 2: 50-step settle (R5 verbatim — best known) ====================
__global__ __launch_bounds__(256, 2) void settle_kernel(
    const float* __restrict__ u1g, const float* __restrict__ u2g,
    const float* __restrict__ W2g, const float* __restrict__ b1g,
    const float* __restrict__ b2g, const int* __restrict__ steps_p,
    float* __restrict__ outg)
{
    __shared__ float c1_s[4 * H];
    __shared__ __align__(16) float r2_s[4][12];
    __shared__ u64 wpart[80 * 33];

    const int tid  = threadIdx.x;
    const int lane = tid & 31;
    const int wid  = tid >> 5;
    const int b0   = blockIdx.x * 4;
    const int nsteps = *steps_p;

    u64 w2p[4][5];
#pragma unroll
    for (int j = 0; j < 4; ++j) {
        const float* w = W2g + (tid + 256 * j) * DOUT;
#pragma unroll
        for (int k = 0; k < 5; ++k)
            w2p[j][k] = pk2(w[2 * k] * 0.0625f, w[2 * k + 1] * 0.0625f);
    }

    float u1v[4][4];
#pragma unroll
    for (int r = 0; r < 4; ++r)
#pragma unroll
        for (int j = 0; j < 4; ++j)
            u1v[r][j] = 0.5f * u1g[(size_t)(b0 + r) * H + tid + 256 * j];

    {
        const float4* xs = (const float4*)(g_xW1 + (size_t)b0 * H);
        const float4* bs = (const float4*)b1g;
        float4* dst = (float4*)c1_s;
#pragma unroll
        for (int i = 0; i < 4; ++i) {
            int e = tid + 256 * i;
            float4 xv = xs[e];
            float4 bv = bs[e & 255];
            dst[e] = make_float4(fmaf(0.03125f, xv.x, 0.0625f * bv.x),
                                 fmaf(0.03125f, xv.y, 0.0625f * bv.y),
                                 fmaf(0.03125f, xv.z, 0.0625f * bv.z),
                                 fmaf(0.03125f, xv.w, 0.0625f * bv.w));
        }
    }

    const bool pb = tid < 160;
    const int r_b  = tid / 40;
    const int rem  = tid - 40 * r_b;
    const int o_b  = rem >> 2;
    const int q4   = rem & 3;
    const int k_b  = o_b >> 1;
    const int half = o_b & 1;
    const float* fb = (const float*)(wpart + ((size_t)((r_b * 5 + k_b) * 4 + q4)) * 33);
    const float* fb_pre = (const float*)(wpart + ((size_t)(k_b * 4 + q4)) * 33);

    {
        u64 qa[5];
#pragma unroll
        for (int k = 0; k < 5; ++k)
            qa[k] = fadd2(fadd2(w2p[0][k], w2p[1][k]), fadd2(w2p[2][k], w2p[3][k]));
#pragma unroll
        for (int k = 0; k < 5; ++k)
            qa[k] = fadd2(qa[k], __shfl_xor_sync(0xffffffffu, qa[k], 16));
        if (lane < 16) {
            int pIdx = wid * 16 + lane;
            int chunk = pIdx >> 5, pos = pIdx & 31;
#pragma unroll
            for (int k = 0; k < 5; ++k)
                wpart[(k * 4 + chunk) * 33 + pos] = qa[k];
        }
    }
    __syncthreads();

    float C2v = 0.0f, wv = 0.0f, r2v = 0.0f;
    if (pb) {
        float s0a = 0, s0b = 0, s1a = 0, s1b = 0;
#pragma unroll
        for (int i = 0; i < 16; ++i) {
            float2 za = *(const float2*)(fb_pre + 4 * i);
            float2 zb = *(const float2*)(fb_pre + 4 * i + 2);
            s0a += za.x; s1a += za.y; s0b += zb.x; s1b += zb.y;
        }
        float s = half ? (s1a + s1b) : (s0a + s0b);
        s += __shfl_xor_sync(0xffffffffu, s, 1);
        s += __shfl_xor_sync(0xffffffffu, s, 2);
        C2v = fmaf(8.0f, s, b2g[o_b]);
        wv  = 0.5f * u2g[(b0 + r_b) * DOUT + o_b];
        float tau = tanh_(wv);
        r2v = fmaf(0.5f, tau, 0.5f);
        if (q4 == 0) r2_s[r_b][o_b] = r2v;
    }
    __syncthreads();

    for (int s = 0; s < nsteps; ++s) {
#pragma unroll
        for (int r = 0; r < 4; ++r) {
            ulonglong2 ra = *(const ulonglong2*)&r2_s[r][0];
            ulonglong2 rb = *(const ulonglong2*)&r2_s[r][4];
            u64 rc = *(const u64*)&r2_s[r][8];
            u64 r2p[5] = {ra.x, ra.y, rb.x, rb.y, rc};
            u64 qacc[5] = {0ULL, 0ULL, 0ULL, 0ULL, 0ULL};
#pragma unroll
            for (int j = 0; j < 4; ++j) {
                float v  = u1v[r][j];
                float th = tanh_(v);
                u64 p2 = fmul2(w2p[j][0], r2p[0]);
                p2 = ffma2(w2p[j][1], r2p[1], p2);
                p2 = ffma2(w2p[j][2], r2p[2], p2);
                p2 = ffma2(w2p[j][3], r2p[3], p2);
                p2 = ffma2(w2p[j][4], r2p[4], p2);
                float pa, pb2; upk2(p2, pa, pb2);
                u64 th2 = pk2(th, th);
#pragma unroll
                for (int k = 0; k < 5; ++k) qacc[k] = ffma2(th2, w2p[j][k], qacc[k]);
                float t   = (pa + pb2) + c1_s[r * H + tid + 256 * j];
                float omt = fmaf(-th, th, 1.0f);
                u1v[r][j] = fmaf(omt, t, 0.5f * v);
            }
#pragma unroll
            for (int k = 0; k < 5; ++k)
                qacc[k] = fadd2(qacc[k], __shfl_xor_sync(0xffffffffu, qacc[k], 16));
            if (lane < 16) {
                int pIdx = wid * 16 + lane;
                int chunk = pIdx >> 5, pos = pIdx & 31;
#pragma unroll
                for (int k = 0; k < 5; ++k)
                    wpart[((r * 5 + k) * 4 + chunk) * 33 + pos] = qacc[k];
            }
        }
        __syncthreads();

        if (pb) {
            float s0a = 0, s0b = 0, s1a = 0, s1b = 0;
#pragma unroll
            for (int i = 0; i < 16; ++i) {
                float2 za = *(const float2*)(fb + 4 * i);
                float2 zb = *(const float2*)(fb + 4 * i + 2);
                s0a += za.x; s1a += za.y; s0b += zb.x; s1b += zb.y;
            }
            float sv = half ? (s1a + s1b) : (s0a + s0b);
            sv += __shfl_xor_sync(0xffffffffu, sv, 1);
            sv += __shfl_xor_sync(0xffffffffu, sv, 2);
            float gq  = fmaf(8.0f, sv, C2v);
            float tau = tanh_(wv);
            float om  = fmaf(-tau, tau, 1.0f);
            wv = fmaf(0.0625f * om, gq, 0.5f * wv);
            r2v = fmaf(0.5f, tanh_(wv), 0.5f);
            if (q4 == 0) r2_s[r_b][o_b] = r2v;
        }
        __syncthreads();
    }

    if (pb && q4 == 0)
        outg[(b0 + r_b) * DOUT + o_b] = r2v;
}

// ==================== launch ====================
extern "C" void kernel_launch(void* const* d_in, const int* in_sizes, int n_in,
                              void* d_out, int out_size) {
    const float* x     = (const float*)d_in[0];
    const float* u1    = (const float*)d_in[1];
    const float* u2    = (const float*)d_in[2];
    const float* W1    = (const float*)d_in[3];
    const float* W2    = (const float*)d_in[4];
    const float* b1    = (const float*)d_in[5];
    const float* b2    = (const float*)d_in[6];
    const int*   steps = (const int*)d_in[7];
    float* out = (float*)d_out;

    const int B = in_sizes[1] / H;

    conv_w1t<<<(H * KPAD + 255) / 256, 256>>>(W1);
    mma_xw1<<<dim3(H / 128, B / 128), 256>>>(x);
    settle_kernel<<<B / 4, 256>>>(u1, u2, W2, b1, b2, steps, out);
}

// round 9
// speedup vs baseline: 1.5475x; 1.0094x over previous
#include <cuda_runtime.h>
#include <cuda_bf16.h>
#include <mma.h>
#include <cstdint>

using namespace nvcuda;

typedef unsigned long long u64;

// ---------------- packed f32x2 helpers ----------------
__device__ __forceinline__ u64 pk2(float a, float b) {
    u64 r; asm("mov.b64 %0, {%1,%2};" : "=l"(r) : "f"(a), "f"(b)); return r;
}
__device__ __forceinline__ void upk2(u64 v, float& a, float& b) {
    asm("mov.b64 {%0,%1}, %2;" : "=f"(a), "=f"(b) : "l"(v));
}
__device__ __forceinline__ u64 ffma2(u64 a, u64 b, u64 c) {
    u64 d; asm("fma.rn.f32x2 %0, %1, %2, %3;" : "=l"(d) : "l"(a), "l"(b), "l"(c)); return d;
}
__device__ __forceinline__ u64 fmul2(u64 a, u64 b) {
    u64 d; asm("mul.rn.f32x2 %0, %1, %2;" : "=l"(d) : "l"(a), "l"(b)); return d;
}
__device__ __forceinline__ u64 fadd2(u64 a, u64 b) {
    u64 d; asm("add.rn.f32x2 %0, %1, %2;" : "=l"(d) : "l"(a), "l"(b)); return d;
}
__device__ __forceinline__ float tanh_(float x) {
    float t; asm("tanh.approx.f32 %0, %1;" : "=f"(t) : "f"(x)); return t;
}

#define H    1024
#define DIN  784
#define DOUT 10
#define MAXB 16384
#define KPAD 832          // W1^T row stride (16B-aligned)
#define NK   49           // 49 * 16 = 784 exactly

__device__ float g_xW1[(size_t)MAXB * H];                        // x @ W1 (fp32)
__device__ __align__(16) __nv_bfloat16 g_wh[(size_t)H * KPAD];   // W1^T hi  [n][k]
__device__ __align__(16) __nv_bfloat16 g_wl[(size_t)H * KPAD];   // W1^T lo  [n][k]

// ==================== conv: W1 -> W1^T hi/lo bf16 (one-time) ====================
__global__ __launch_bounds__(256) void conv_w1t(const float* __restrict__ W1) {
    int u = blockIdx.x * 256 + threadIdx.x;
    if (u >= H * KPAD) return;
    int n = u / KPAD, k = u - n * KPAD;
    __nv_bfloat16 h = __ushort_as_bfloat16(0), l = __ushort_as_bfloat16(0);
    if (k < DIN) {
        float w = W1[(size_t)k * H + n];
        h = __float2bfloat16(w);
        l = __float2bfloat16(w - __bfloat162float(h));
    }
    g_wh[(size_t)n * KPAD + k] = h;
    g_wl[(size_t)n * KPAD + k] = l;
}

// ==================== split-bf16 mma.sync GEMM, cp.async pipelined ====================
// g_xW1 = x @ W1. CTA tile 128x128, K-step 16, 49 iters, ONE __syncthreads/iter.
// smem row stride 24 elems (48B) -> bank-distinct rows for ldmatrix (no conflicts).
// Tiles live in DYNAMIC smem (61.4 KB > 48 KB static limit; opt-in via attribute).
// A (x): fp32 LDG -> hi/lo bf16 split in regs -> STS, 2-stage.
// B (W1^T hi/lo): cp.async.cg, 3-stage ring, wait_group 1 (one group in flight).
// acc += Ah*Bh + Ah*Bl + Al*Bh  (fp32 accumulate).
#define TSW   24                    // smem tile k-stride in bf16 elements
#define TILE  (128 * TSW)           // 3072 bf16 = 6144 B per tile
#define MMA_SMEM_BYTES ((2 + 2 + 3 + 3) * TILE * 2)   // 61440

__device__ __forceinline__ void cp16(uint32_t dst, const void* src) {
    asm volatile("cp.async.cg.shared.global [%0], [%1], 16;" :: "r"(dst), "l"(src));
}

__global__ __launch_bounds__(256, 2) void mma_xw1(const float* __restrict__ x) {
    extern __shared__ __nv_bfloat16 smem_dyn[];
    __nv_bfloat16* sAh = smem_dyn;                 // [2][TILE]
    __nv_bfloat16* sAl = sAh + 2 * TILE;           // [2][TILE]
    __nv_bfloat16* sBh = sAl + 2 * TILE;           // [3][TILE]
    __nv_bfloat16* sBl = sBh + 3 * TILE;           // [3][TILE]

    const int tid  = threadIdx.x;
    const int warp = tid >> 5;
    const int m0 = blockIdx.y * 128;
    const int n0 = blockIdx.x * 128;
    const int wm = (warp >> 2) * 64;
    const int wn = (warp & 3) * 32;

    wmma::fragment<wmma::accumulator, 16, 16, 16, float> acc[4][2];
#pragma unroll
    for (int i = 0; i < 4; ++i)
#pragma unroll
        for (int j = 0; j < 2; ++j) wmma::fill_fragment(acc[i][j], 0.0f);

    // fill mapping: 2 threads per row, 8 elements (16B bf16) each
    const int row = tid >> 1;
    const int ch  = (tid & 1) * 8;
    const float* xsrc = x + (size_t)(m0 + row) * DIN + ch;
    const __nv_bfloat16* bhsrc = g_wh + (size_t)(n0 + row) * KPAD + ch;
    const __nv_bfloat16* blsrc = g_wl + (size_t)(n0 + row) * KPAD + ch;
    const int sidx = row * TSW + ch;

    float4 aPre0, aPre1;
    auto ldA = [&](int it) { aPre0 = *(const float4*)(xsrc + it * 16);
                             aPre1 = *(const float4*)(xsrc + it * 16 + 4); };
    auto stA = [&](int stg) {
        float v[8] = {aPre0.x, aPre0.y, aPre0.z, aPre0.w, aPre1.x, aPre1.y, aPre1.z, aPre1.w};
        ushort hh[8], ll[8];
#pragma unroll
        for (int i = 0; i < 8; ++i) {
            __nv_bfloat16 h = __float2bfloat16(v[i]);
            __nv_bfloat16 l = __float2bfloat16(v[i] - __bfloat162float(h));
            hh[i] = __bfloat16_as_ushort(h);
            ll[i] = __bfloat16_as_ushort(l);
        }
        *(ushort4*)&sAh[stg * TILE + sidx]     = make_ushort4(hh[0], hh[1], hh[2], hh[3]);
        *(ushort4*)&sAh[stg * TILE + sidx + 4] = make_ushort4(hh[4], hh[5], hh[6], hh[7]);
        *(ushort4*)&sAl[stg * TILE + sidx]     = make_ushort4(ll[0], ll[1], ll[2], ll[3]);
        *(ushort4*)&sAl[stg * TILE + sidx + 4] = make_ushort4(ll[4], ll[5], ll[6], ll[7]);
    };
    auto cpB = [&](int it, int stg) {
        cp16((uint32_t)__cvta_generic_to_shared(&sBh[stg * TILE + sidx]), bhsrc + it * 16);
        cp16((uint32_t)__cvta_generic_to_shared(&sBl[stg * TILE + sidx]), blsrc + it * 16);
        asm volatile("cp.async.commit_group;" ::: "memory");
    };

    // ---- prologue: B(0), B(1) in flight; A(0) in smem; A(1) in regs ----
    cpB(0, 0);
    cpB(1, 1);
    ldA(0); stA(0);
    ldA(1);

    for (int it = 0; it < NK; ++it) {
        if (it < NK - 1) { asm volatile("cp.async.wait_group 1;" ::: "memory"); }
        else             { asm volatile("cp.async.wait_group 0;" ::: "memory"); }
        __syncthreads();                  // B(it) resident; A-stage (it+1)&1 free to refill
        if (it + 1 < NK) stA((it + 1) & 1);
        if (it + 2 < NK) { cpB(it + 2, (it + 2) % 3); ldA(it + 2); }

        const int sa = it & 1;
        const int sb = it % 3;
        wmma::fragment<wmma::matrix_b, 16, 16, 16, __nv_bfloat16, wmma::col_major> bh[2], bl[2];
#pragma unroll
        for (int j = 0; j < 2; ++j) {
            wmma::load_matrix_sync(bh[j], &sBh[sb * TILE + (wn + j * 16) * TSW], TSW);
            wmma::load_matrix_sync(bl[j], &sBl[sb * TILE + (wn + j * 16) * TSW], TSW);
        }
#pragma unroll
        for (int i = 0; i < 4; ++i) {
            wmma::fragment<wmma::matrix_a, 16, 16, 16, __nv_bfloat16, wmma::row_major> ah, al;
            wmma::load_matrix_sync(ah, &sAh[sa * TILE + (wm + i * 16) * TSW], TSW);
            wmma::load_matrix_sync(al, &sAl[sa * TILE + (wm + i * 16) * TSW], TSW);
#pragma unroll
            for (int j = 0; j < 2; ++j) {
                wmma::mma_sync(acc[i][j], ah, bh[j], acc[i][j]);
                wmma::mma_sync(acc[i][j], ah, bl[j], acc[i][j]);
                wmma::mma_sync(acc[i][j], al, bh[j], acc[i][j]);
            }
        }
    }

#pragma unroll
    for (int i = 0; i < 4; ++i)
#pragma unroll
        for (int j = 0; j < 2; ++j) {
            float* C = g_xW1 + (size_t)(m0 + wm + i * 16) * H + (n0 + wn + j * 16);
            wmma::store_matrix_sync(C, acc[i][j], H, wmma::mem_row_major);
        }
}

// ==================== Kernel 2: 50-step settle (R5 verbatim — best known) ====================
__global__ __launch_bounds__(256, 2) void settle_kernel(
    const float* __restrict__ u1g, const float* __restrict__ u2g,
    const float* __restrict__ W2g, const float* __restrict__ b1g,
    const float* __restrict__ b2g, const int* __restrict__ steps_p,
    float* __restrict__ outg)
{
    __shared__ float c1_s[4 * H];
    __shared__ __align__(16) float r2_s[4][12];
    __shared__ u64 wpart[80 * 33];

    const int tid  = threadIdx.x;
    const int lane = tid & 31;
    const int wid  = tid >> 5;
    const int b0   = blockIdx.x * 4;
    const int nsteps = *steps_p;

    u64 w2p[4][5];
#pragma unroll
    for (int j = 0; j < 4; ++j) {
        const float* w = W2g + (tid + 256 * j) * DOUT;
#pragma unroll
        for (int k = 0; k < 5; ++k)
            w2p[j][k] = pk2(w[2 * k] * 0.0625f, w[2 * k + 1] * 0.0625f);
    }

    float u1v[4][4];
#pragma unroll
    for (int r = 0; r < 4; ++r)
#pragma unroll
        for (int j = 0; j < 4; ++j)
            u1v[r][j] = 0.5f * u1g[(size_t)(b0 + r) * H + tid + 256 * j];

    {
        const float4* xs = (const float4*)(g_xW1 + (size_t)b0 * H);
        const float4* bs = (const float4*)b1g;
        float4* dst = (float4*)c1_s;
#pragma unroll
        for (int i = 0; i < 4; ++i) {
            int e = tid + 256 * i;
            float4 xv = xs[e];
            float4 bv = bs[e & 255];
            dst[e] = make_float4(fmaf(0.03125f, xv.x, 0.0625f * bv.x),
                                 fmaf(0.03125f, xv.y, 0.0625f * bv.y),
                                 fmaf(0.03125f, xv.z, 0.0625f * bv.z),
                                 fmaf(0.03125f, xv.w, 0.0625f * bv.w));
        }
    }

    const bool pb = tid < 160;
    const int r_b  = tid / 40;
    const int rem  = tid - 40 * r_b;
    const int o_b  = rem >> 2;
    const int q4   = rem & 3;
    const int k_b  = o_b >> 1;
    const int half = o_b & 1;
    const float* fb = (const float*)(wpart + ((size_t)((r_b * 5 + k_b) * 4 + q4)) * 33);
    const float* fb_pre = (const float*)(wpart + ((size_t)(k_b * 4 + q4)) * 33);

    {
        u64 qa[5];
#pragma unroll
        for (int k = 0; k < 5; ++k)
            qa[k] = fadd2(fadd2(w2p[0][k], w2p[1][k]), fadd2(w2p[2][k], w2p[3][k]));
#pragma unroll
        for (int k = 0; k < 5; ++k)
            qa[k] = fadd2(qa[k], __shfl_xor_sync(0xffffffffu, qa[k], 16));
        if (lane < 16) {
            int pIdx = wid * 16 + lane;
            int chunk = pIdx >> 5, pos = pIdx & 31;
#pragma unroll
            for (int k = 0; k < 5; ++k)
                wpart[(k * 4 + chunk) * 33 + pos] = qa[k];
        }
    }
    __syncthreads();

    float C2v = 0.0f, wv = 0.0f, r2v = 0.0f;
    if (pb) {
        float s0a = 0, s0b = 0, s1a = 0, s1b = 0;
#pragma unroll
        for (int i = 0; i < 16; ++i) {
            float2 za = *(const float2*)(fb_pre + 4 * i);
            float2 zb = *(const float2*)(fb_pre + 4 * i + 2);
            s0a += za.x; s1a += za.y; s0b += zb.x; s1b += zb.y;
        }
        float s = half ? (s1a + s1b) : (s0a + s0b);
        s += __shfl_xor_sync(0xffffffffu, s, 1);
        s += __shfl_xor_sync(0xffffffffu, s, 2);
        C2v = fmaf(8.0f, s, b2g[o_b]);
        wv  = 0.5f * u2g[(b0 + r_b) * DOUT + o_b];
        float tau = tanh_(wv);
        r2v = fmaf(0.5f, tau, 0.5f);
        if (q4 == 0) r2_s[r_b][o_b] = r2v;
    }
    __syncthreads();

    for (int s = 0; s < nsteps; ++s) {
#pragma unroll
        for (int r = 0; r < 4; ++r) {
            ulonglong2 ra = *(const ulonglong2*)&r2_s[r][0];
            ulonglong2 rb = *(const ulonglong2*)&r2_s[r][4];
            u64 rc = *(const u64*)&r2_s[r][8];
            u64 r2p[5] = {ra.x, ra.y, rb.x, rb.y, rc};
            u64 qacc[5] = {0ULL, 0ULL, 0ULL, 0ULL, 0ULL};
#pragma unroll
            for (int j = 0; j < 4; ++j) {
                float v  = u1v[r][j];
                float th = tanh_(v);
                u64 p2 = fmul2(w2p[j][0], r2p[0]);
                p2 = ffma2(w2p[j][1], r2p[1], p2);
                p2 = ffma2(w2p[j][2], r2p[2], p2);
                p2 = ffma2(w2p[j][3], r2p[3], p2);
                p2 = ffma2(w2p[j][4], r2p[4], p2);
                float pa, pb2; upk2(p2, pa, pb2);
                u64 th2 = pk2(th, th);
#pragma unroll
                for (int k = 0; k < 5; ++k) qacc[k] = ffma2(th2, w2p[j][k], qacc[k]);
                float t   = (pa + pb2) + c1_s[r * H + tid + 256 * j];
                float omt = fmaf(-th, th, 1.0f);
                u1v[r][j] = fmaf(omt, t, 0.5f * v);
            }
#pragma unroll
            for (int k = 0; k < 5; ++k)
                qacc[k] = fadd2(qacc[k], __shfl_xor_sync(0xffffffffu, qacc[k], 16));
            if (lane < 16) {
                int pIdx = wid * 16 + lane;
                int chunk = pIdx >> 5, pos = pIdx & 31;
#pragma unroll
                for (int k = 0; k < 5; ++k)
                    wpart[((r * 5 + k) * 4 + chunk) * 33 + pos] = qacc[k];
            }
        }
        __syncthreads();

        if (pb) {
            float s0a = 0, s0b = 0, s1a = 0, s1b = 0;
#pragma unroll
            for (int i = 0; i < 16; ++i) {
                float2 za = *(const float2*)(fb + 4 * i);
                float2 zb = *(const float2*)(fb + 4 * i + 2);
                s0a += za.x; s1a += za.y; s0b += zb.x; s1b += zb.y;
            }
            float sv = half ? (s1a + s1b) : (s0a + s0b);
            sv += __shfl_xor_sync(0xffffffffu, sv, 1);
            sv += __shfl_xor_sync(0xffffffffu, sv, 2);
            float gq  = fmaf(8.0f, sv, C2v);
            float tau = tanh_(wv);
            float om  = fmaf(-tau, tau, 1.0f);
            wv = fmaf(0.0625f * om, gq, 0.5f * wv);
            r2v = fmaf(0.5f, tanh_(wv), 0.5f);
            if (q4 == 0) r2_s[r_b][o_b] = r2v;
        }
        __syncthreads();
    }

    if (pb && q4 == 0)
        outg[(b0 + r_b) * DOUT + o_b] = r2v;
}

// ==================== launch ====================
extern "C" void kernel_launch(void* const* d_in, const int* in_sizes, int n_in,
                              void* d_out, int out_size) {
    const float* x     = (const float*)d_in[0];
    const float* u1    = (const float*)d_in[1];
    const float* u2    = (const float*)d_in[2];
    const float* W1    = (const float*)d_in[3];
    const float* W2    = (const float*)d_in[4];
    const float* b1    = (const float*)d_in[5];
    const float* b2    = (const float*)d_in[6];
    const int*   steps = (const int*)d_in[7];
    float* out = (float*)d_out;

    const int B = in_sizes[1] / H;

    cudaFuncSetAttribute(mma_xw1, cudaFuncAttributeMaxDynamicSharedMemorySize,
                         MMA_SMEM_BYTES);

    conv_w1t<<<(H * KPAD + 255) / 256, 256>>>(W1);
    mma_xw1<<<dim3(H / 128, B / 128), 256, MMA_SMEM_BYTES>>>(x);
    settle_kernel<<<B / 4, 256>>>(u1, u2, W2, b1, b2, steps, out);
}

// round 11
// speedup vs baseline: 1.7025x; 1.1002x over previous
#include <cuda_runtime.h>
#include <cuda_fp16.h>
#include <mma.h>
#include <cstdint>

using namespace nvcuda;

typedef unsigned long long u64;

// ---------------- packed f32x2 helpers ----------------
__device__ __forceinline__ u64 pk2(float a, float b) {
    u64 r; asm("mov.b64 %0, {%1,%2};" : "=l"(r) : "f"(a), "f"(b)); return r;
}
__device__ __forceinline__ void upk2(u64 v, float& a, float& b) {
    asm("mov.b64 {%0,%1}, %2;" : "=f"(a), "=f"(b) : "l"(v));
}
__device__ __forceinline__ u64 ffma2(u64 a, u64 b, u64 c) {
    u64 d; asm("fma.rn.f32x2 %0, %1, %2, %3;" : "=l"(d) : "l"(a), "l"(b), "l"(c)); return d;
}
__device__ __forceinline__ u64 fmul2(u64 a, u64 b) {
    u64 d; asm("mul.rn.f32x2 %0, %1, %2;" : "=l"(d) : "l"(a), "l"(b)); return d;
}
__device__ __forceinline__ u64 fadd2(u64 a, u64 b) {
    u64 d; asm("add.rn.f32x2 %0, %1, %2;" : "=l"(d) : "l"(a), "l"(b)); return d;
}
__device__ __forceinline__ float tanh_(float x) {
    float t; asm("tanh.approx.f32 %0, %1;" : "=f"(t) : "f"(x)); return t;
}

#define H    1024
#define DIN  784
#define DOUT 10
#define MAXB 16384
#define NK   49           // 49 * 16 = 784 exactly

__device__ float g_xW1[(size_t)MAXB * H];   // x @ W1 (fp32)

// ==================== fp16 single-MMA GEMM: g_xW1 = x @ W1 ====================
// CTA tile 128x128, K-step 16, 49 iters, ONE __syncthreads/iter, 2-stage ring.
// A = x (fp32 -> fp16 in regs -> STS), row-major a-frag, row stride 24 (48B,
// bank-distinct). B = W1 consumed DIRECTLY as row-major b-frag (element (k,n)
// at k*H+n): tile [16][144] fp16, 288B rows -> 2-phase conflict-free ldmatrix.
// No transpose/conv kernel needed. fp32 accumulate.
#define TSW  24    // A smem k-stride (fp16 elems)
#define BSTR 144   // B smem n-stride (fp16 elems)

__global__ __launch_bounds__(256, 2) void mma_xw1(const float* __restrict__ x,
                                                  const float* __restrict__ W1) {
    __shared__ __half sA[2][128 * TSW];   // 12.3 KB
    __shared__ __half sB[2][16 * BSTR];   // 9.2 KB

    const int tid  = threadIdx.x;
    const int warp = tid >> 5;
    const int m0 = blockIdx.y * 128;
    const int n0 = blockIdx.x * 128;
    const int wm = (warp >> 2) * 64;
    const int wn = (warp & 3) * 32;

    wmma::fragment<wmma::accumulator, 16, 16, 16, float> acc[4][2];
#pragma unroll
    for (int i = 0; i < 4; ++i)
#pragma unroll
        for (int j = 0; j < 2; ++j) wmma::fill_fragment(acc[i][j], 0.0f);

    // A fill: 2 threads/row, 8 floats each. B fill: 16 threads/k-row, 8 floats each.
    const int arow = tid >> 1, ach = (tid & 1) * 8;
    const float* asrc = x + (size_t)(m0 + arow) * DIN + ach;
    const int aidx = arow * TSW + ach;
    const int bkr = tid >> 4, bnc = (tid & 15) * 8;
    const float* bsrc = W1 + (size_t)bkr * H + n0 + bnc;
    const int bidx = bkr * BSTR + bnc;

    float4 a0, a1, b0, b1;
    auto ld = [&](int it) {
        a0 = *(const float4*)(asrc + it * 16);
        a1 = *(const float4*)(asrc + it * 16 + 4);
        b0 = *(const float4*)(bsrc + (size_t)it * 16 * H);
        b1 = *(const float4*)(bsrc + (size_t)it * 16 * H + 4);
    };
    auto st = [&](int s) {
        float va[8] = {a0.x, a0.y, a0.z, a0.w, a1.x, a1.y, a1.z, a1.w};
        float vb[8] = {b0.x, b0.y, b0.z, b0.w, b1.x, b1.y, b1.z, b1.w};
        ushort ha[8], hb[8];
#pragma unroll
        for (int i = 0; i < 8; ++i) {
            ha[i] = __half_as_ushort(__float2half_rn(va[i]));
            hb[i] = __half_as_ushort(__float2half_rn(vb[i]));
        }
        *(ushort4*)&sA[s][aidx]     = make_ushort4(ha[0], ha[1], ha[2], ha[3]);
        *(ushort4*)&sA[s][aidx + 4] = make_ushort4(ha[4], ha[5], ha[6], ha[7]);
        *(ushort4*)&sB[s][bidx]     = make_ushort4(hb[0], hb[1], hb[2], hb[3]);
        *(ushort4*)&sB[s][bidx + 4] = make_ushort4(hb[4], hb[5], hb[6], hb[7]);
    };

    ld(0); st(0);
    ld(1);

    for (int it = 0; it < NK; ++it) {
        __syncthreads();                   // stage[it&1] visible; prior reads done
        if (it + 1 < NK) st((it + 1) & 1);
        if (it + 2 < NK) ld(it + 2);

        const int s = it & 1;
        wmma::fragment<wmma::matrix_b, 16, 16, 16, __half, wmma::row_major> bf[2];
#pragma unroll
        for (int j = 0; j < 2; ++j)
            wmma::load_matrix_sync(bf[j], &sB[s][wn + j * 16], BSTR);
#pragma unroll
        for (int i = 0; i < 4; ++i) {
            wmma::fragment<wmma::matrix_a, 16, 16, 16, __half, wmma::row_major> af;
            wmma::load_matrix_sync(af, &sA[s][(wm + i * 16) * TSW], TSW);
#pragma unroll
            for (int j = 0; j < 2; ++j)
                wmma::mma_sync(acc[i][j], af, bf[j], acc[i][j]);
        }
    }

#pragma unroll
    for (int i = 0; i < 4; ++i)
#pragma unroll
        for (int j = 0; j < 2; ++j) {
            float* C = g_xW1 + (size_t)(m0 + wm + i * 16) * H + (n0 + wn + j * 16);
            wmma::store_matrix_sync(C, acc[i][j], H, wmma::mem_row_major);
        }
}

// ==================== Kernel 2: 50-step settle (R5 verbatim — best known) ====================
__global__ __launch_bounds__(256, 2) void settle_kernel(
    const float* __restrict__ u1g, const float* __restrict__ u2g,
    const float* __restrict__ W2g, const float* __restrict__ b1g,
    const float* __restrict__ b2g, const int* __restrict__ steps_p,
    float* __restrict__ outg)
{
    __shared__ float c1_s[4 * H];
    __shared__ __align__(16) float r2_s[4][12];
    __shared__ u64 wpart[80 * 33];

    const int tid  = threadIdx.x;
    const int lane = tid & 31;
    const int wid  = tid >> 5;
    const int b0   = blockIdx.x * 4;
    const int nsteps = *steps_p;

    u64 w2p[4][5];
#pragma unroll
    for (int j = 0; j < 4; ++j) {
        const float* w = W2g + (tid + 256 * j) * DOUT;
#pragma unroll
        for (int k = 0; k < 5; ++k)
            w2p[j][k] = pk2(w[2 * k] * 0.0625f, w[2 * k + 1] * 0.0625f);
    }

    float u1v[4][4];
#pragma unroll
    for (int r = 0; r < 4; ++r)
#pragma unroll
        for (int j = 0; j < 4; ++j)
            u1v[r][j] = 0.5f * u1g[(size_t)(b0 + r) * H + tid + 256 * j];

    {
        const float4* xs = (const float4*)(g_xW1 + (size_t)b0 * H);
        const float4* bs = (const float4*)b1g;
        float4* dst = (float4*)c1_s;
#pragma unroll
        for (int i = 0; i < 4; ++i) {
            int e = tid + 256 * i;
            float4 xv = xs[e];
            float4 bv = bs[e & 255];
            dst[e] = make_float4(fmaf(0.03125f, xv.x, 0.0625f * bv.x),
                                 fmaf(0.03125f, xv.y, 0.0625f * bv.y),
                                 fmaf(0.03125f, xv.z, 0.0625f * bv.z),
                                 fmaf(0.03125f, xv.w, 0.0625f * bv.w));
        }
    }

    const bool pb = tid < 160;
    const int r_b  = tid / 40;
    const int rem  = tid - 40 * r_b;
    const int o_b  = rem >> 2;
    const int q4   = rem & 3;
    const int k_b  = o_b >> 1;
    const int half = o_b & 1;
    const float* fb = (const float*)(wpart + ((size_t)((r_b * 5 + k_b) * 4 + q4)) * 33);
    const float* fb_pre = (const float*)(wpart + ((size_t)(k_b * 4 + q4)) * 33);

    {
        u64 qa[5];
#pragma unroll
        for (int k = 0; k < 5; ++k)
            qa[k] = fadd2(fadd2(w2p[0][k], w2p[1][k]), fadd2(w2p[2][k], w2p[3][k]));
#pragma unroll
        for (int k = 0; k < 5; ++k)
            qa[k] = fadd2(qa[k], __shfl_xor_sync(0xffffffffu, qa[k], 16));
        if (lane < 16) {
            int pIdx = wid * 16 + lane;
            int chunk = pIdx >> 5, pos = pIdx & 31;
#pragma unroll
            for (int k = 0; k < 5; ++k)
                wpart[(k * 4 + chunk) * 33 + pos] = qa[k];
        }
    }
    __syncthreads();

    float C2v = 0.0f, wv = 0.0f, r2v = 0.0f;
    if (pb) {
        float s0a = 0, s0b = 0, s1a = 0, s1b = 0;
#pragma unroll
        for (int i = 0; i < 16; ++i) {
            float2 za = *(const float2*)(fb_pre + 4 * i);
            float2 zb = *(const float2*)(fb_pre + 4 * i + 2);
            s0a += za.x; s1a += za.y; s0b += zb.x; s1b += zb.y;
        }
        float s = half ? (s1a + s1b) : (s0a + s0b);
        s += __shfl_xor_sync(0xffffffffu, s, 1);
        s += __shfl_xor_sync(0xffffffffu, s, 2);
        C2v = fmaf(8.0f, s, b2g[o_b]);
        wv  = 0.5f * u2g[(b0 + r_b) * DOUT + o_b];
        float tau = tanh_(wv);
        r2v = fmaf(0.5f, tau, 0.5f);
        if (q4 == 0) r2_s[r_b][o_b] = r2v;
    }
    __syncthreads();

    for (int s = 0; s < nsteps; ++s) {
#pragma unroll
        for (int r = 0; r < 4; ++r) {
            ulonglong2 ra = *(const ulonglong2*)&r2_s[r][0];
            ulonglong2 rb = *(const ulonglong2*)&r2_s[r][4];
            u64 rc = *(const u64*)&r2_s[r][8];
            u64 r2p[5] = {ra.x, ra.y, rb.x, rb.y, rc};
            u64 qacc[5] = {0ULL, 0ULL, 0ULL, 0ULL, 0ULL};
#pragma unroll
            for (int j = 0; j < 4; ++j) {
                float v  = u1v[r][j];
                float th = tanh_(v);
                u64 p2 = fmul2(w2p[j][0], r2p[0]);
                p2 = ffma2(w2p[j][1], r2p[1], p2);
                p2 = ffma2(w2p[j][2], r2p[2], p2);
                p2 = ffma2(w2p[j][3], r2p[3], p2);
                p2 = ffma2(w2p[j][4], r2p[4], p2);
                float pa, pb2; upk2(p2, pa, pb2);
                u64 th2 = pk2(th, th);
#pragma unroll
                for (int k = 0; k < 5; ++k) qacc[k] = ffma2(th2, w2p[j][k], qacc[k]);
                float t   = (pa + pb2) + c1_s[r * H + tid + 256 * j];
                float omt = fmaf(-th, th, 1.0f);
                u1v[r][j] = fmaf(omt, t, 0.5f * v);
            }
#pragma unroll
            for (int k = 0; k < 5; ++k)
                qacc[k] = fadd2(qacc[k], __shfl_xor_sync(0xffffffffu, qacc[k], 16));
            if (lane < 16) {
                int pIdx = wid * 16 + lane;
                int chunk = pIdx >> 5, pos = pIdx & 31;
#pragma unroll
                for (int k = 0; k < 5; ++k)
                    wpart[((r * 5 + k) * 4 + chunk) * 33 + pos] = qacc[k];
            }
        }
        __syncthreads();

        if (pb) {
            float s0a = 0, s0b = 0, s1a = 0, s1b = 0;
#pragma unroll
            for (int i = 0; i < 16; ++i) {
                float2 za = *(const float2*)(fb + 4 * i);
                float2 zb = *(const float2*)(fb + 4 * i + 2);
                s0a += za.x; s1a += za.y; s0b += zb.x; s1b += zb.y;
            }
            float sv = half ? (s1a + s1b) : (s0a + s0b);
            sv += __shfl_xor_sync(0xffffffffu, sv, 1);
            sv += __shfl_xor_sync(0xffffffffu, sv, 2);
            float gq  = fmaf(8.0f, sv, C2v);
            float tau = tanh_(wv);
            float om  = fmaf(-tau, tau, 1.0f);
            wv = fmaf(0.0625f * om, gq, 0.5f * wv);
            r2v = fmaf(0.5f, tanh_(wv), 0.5f);
            if (q4 == 0) r2_s[r_b][o_b] = r2v;
        }
        __syncthreads();
    }

    if (pb && q4 == 0)
        outg[(b0 + r_b) * DOUT + o_b] = r2v;
}

// ==================== launch ====================
extern "C" void kernel_launch(void* const* d_in, const int* in_sizes, int n_in,
                              void* d_out, int out_size) {
    const float* x     = (const float*)d_in[0];
    const float* u1    = (const float*)d_in[1];
    const float* u2    = (const float*)d_in[2];
    const float* W1    = (const float*)d_in[3];
    const float* W2    = (const float*)d_in[4];
    const float* b1    = (const float*)d_in[5];
    const float* b2    = (const float*)d_in[6];
    const int*   steps = (const int*)d_in[7];
    float* out = (float*)d_out;

    const int B = in_sizes[1] / H;

    mma_xw1<<<dim3(H / 128, B / 128), 256>>>(x, W1);
    settle_kernel<<<B / 4, 256>>>(u1, u2, W2, b1, b2, steps, out);
}